// round 1
// baseline (speedup 1.0000x reference)
#include <cuda_runtime.h>

#define NMAX   50000
#define DIMK   256
#define HN     4
#define CN     64
#define EMAX   800000
#define NEG_SLOPE 0.2f
#define LN_EPS 1e-5f

// ---------------- static device scratch (no allocations allowed) ------------
__device__ float g_B[DIMK * 512];          // concat(W, W_res) columns: 512 KB
__device__ float g_h[NMAX * DIMK];         // h = x@W              : 51 MB
__device__ float g_acc[NMAX * DIMK];       // accumulator y        : 51 MB
__device__ float g_als[NMAX * HN];         // attn logits (src side)
__device__ float g_ald[NMAX * HN];         // attn logits (dst side)
__device__ float g_den[NMAX * HN];         // softmax denominators
__device__ int   g_src[EMAX];
__device__ int   g_dst[EMAX];
__device__ int   g_is64;

// ---------------- K0: stage B = [W | W_res] ---------------------------------
__global__ void k_copyB(const float* __restrict__ W, const float* __restrict__ Wres) {
    int idx = blockIdx.x * blockDim.x + threadIdx.x;   // 0 .. 256*128-1
    if (idx >= DIMK * 128) return;
    int k  = idx >> 7;        // row 0..255
    int j  = (idx & 127) * 4; // col 0..508
    float4 v;
    if (j < 256) v = *(const float4*)&W[k * 256 + j];
    else         v = *(const float4*)&Wres[k * 256 + j - 256];
    *(float4*)&g_B[k * 512 + j] = v;
}

// ---------------- K1: fused GEMM  X[n,256] @ B[256,512] ---------------------
// cols 0..255 -> g_h ; cols 256..511 -> g_acc = x@W_res + b_res + bias_gat
__global__ __launch_bounds__(256) void k_gemm(const float* __restrict__ X,
                                              const float* __restrict__ b_res,
                                              const float* __restrict__ bias_gat,
                                              int n) {
    __shared__ float As[16][65];    // transposed A tile, padded
    __shared__ float Bs[16][128];
    int t  = threadIdx.x;
    int tr = t >> 5;                // 0..7  (8 rows of 8)
    int tc = t & 31;                // 0..31 (32 cols of 4)
    int rowBase = blockIdx.y * 64;
    int colBase = blockIdx.x * 128;

    float acc[8][4];
    #pragma unroll
    for (int i = 0; i < 8; i++)
        #pragma unroll
        for (int j = 0; j < 4; j++) acc[i][j] = 0.f;

    int aRow = t >> 2;              // 0..63
    int aC4  = (t & 3) * 4;         // 0,4,8,12

    for (int k0 = 0; k0 < 256; k0 += 16) {
        // load A tile (64x16), transpose into smem
        float4 av = make_float4(0.f, 0.f, 0.f, 0.f);
        int gr = rowBase + aRow;
        if (gr < n) av = *(const float4*)&X[gr * 256 + k0 + aC4];
        As[aC4 + 0][aRow] = av.x;
        As[aC4 + 1][aRow] = av.y;
        As[aC4 + 2][aRow] = av.z;
        As[aC4 + 3][aRow] = av.w;
        // load B tile (16x128), 2 float4 per thread
        #pragma unroll
        for (int q = 0; q < 2; q++) {
            int idx = t + q * 256;
            int br  = idx >> 5;
            int bc  = (idx & 31) * 4;
            *(float4*)&Bs[br][bc] =
                *(const float4*)&g_B[(k0 + br) * 512 + colBase + bc];
        }
        __syncthreads();
        #pragma unroll
        for (int kk = 0; kk < 16; kk++) {
            float a[8];
            #pragma unroll
            for (int i = 0; i < 8; i++) a[i] = As[kk][tr * 8 + i];
            float4 b = *(float4*)&Bs[kk][tc * 4];
            #pragma unroll
            for (int i = 0; i < 8; i++) {
                acc[i][0] += a[i] * b.x;
                acc[i][1] += a[i] * b.y;
                acc[i][2] += a[i] * b.z;
                acc[i][3] += a[i] * b.w;
            }
        }
        __syncthreads();
    }
    // epilogue
    #pragma unroll
    for (int i = 0; i < 8; i++) {
        int gr = rowBase + tr * 8 + i;
        if (gr >= n) continue;
        int gc = colBase + tc * 4;
        if (gc < 256) {
            *(float4*)&g_h[gr * 256 + gc] =
                make_float4(acc[i][0], acc[i][1], acc[i][2], acc[i][3]);
        } else {
            int c = gc - 256;
            float4 bb = *(const float4*)&b_res[c];
            float4 bg = *(const float4*)&bias_gat[c];
            *(float4*)&g_acc[gr * 256 + c] =
                make_float4(acc[i][0] + bb.x + bg.x, acc[i][1] + bb.y + bg.y,
                            acc[i][2] + bb.z + bg.z, acc[i][3] + bb.w + bg.w);
        }
    }
}

// ---------------- K2: per-node attention logits + denom init ----------------
// warp per node: al_src[i][h] = sum_c h[i][h*64+c]*a_src[h][c] ; same for dst
__global__ void k_al(const float* __restrict__ a_src,
                     const float* __restrict__ a_dst, int n) {
    int warp = (blockIdx.x * blockDim.x + threadIdx.x) >> 5;
    int lane = threadIdx.x & 31;
    if (warp >= n) return;
    const float* hrow = &g_h[warp * 256];
    float4 h1 = *(const float4*)&hrow[lane * 4];
    float4 h2 = *(const float4*)&hrow[128 + lane * 4];
    float4 a1 = *(const float4*)&a_src[lane * 4];
    float4 a2 = *(const float4*)&a_src[128 + lane * 4];
    float4 c1 = *(const float4*)&a_dst[lane * 4];
    float4 c2 = *(const float4*)&a_dst[128 + lane * 4];
    float s1 = h1.x*a1.x + h1.y*a1.y + h1.z*a1.z + h1.w*a1.w;  // heads 0/1
    float s2 = h2.x*a2.x + h2.y*a2.y + h2.z*a2.z + h2.w*a2.w;  // heads 2/3
    float d1 = h1.x*c1.x + h1.y*c1.y + h1.z*c1.z + h1.w*c1.w;
    float d2 = h2.x*c2.x + h2.y*c2.y + h2.z*c2.z + h2.w*c2.w;
    // reduce within each 16-lane half (xor keeps lane/16 invariant)
    #pragma unroll
    for (int off = 8; off >= 1; off >>= 1) {
        s1 += __shfl_xor_sync(0xffffffffu, s1, off);
        s2 += __shfl_xor_sync(0xffffffffu, s2, off);
        d1 += __shfl_xor_sync(0xffffffffu, d1, off);
        d2 += __shfl_xor_sync(0xffffffffu, d2, off);
    }
    if (lane == 0) {
        g_als[warp * 4 + 0] = s1;  g_als[warp * 4 + 2] = s2;
        g_ald[warp * 4 + 0] = d1;  g_ald[warp * 4 + 2] = d2;
        g_den[warp * 4 + 0] = 0.f; g_den[warp * 4 + 1] = 0.f;
        g_den[warp * 4 + 2] = 0.f; g_den[warp * 4 + 3] = 0.f;
    } else if (lane == 16) {
        g_als[warp * 4 + 1] = s1;  g_als[warp * 4 + 3] = s2;
        g_ald[warp * 4 + 1] = d1;  g_ald[warp * 4 + 3] = d2;
    }
}

// ---------------- K3a/b: edge-index dtype detect + convert ------------------
__global__ void k_detect(const void* __restrict__ ei, int n) {
    // If interpreting the buffer as int64 yields 32 in-range values, it is
    // int64. (int32 data interpreted as int64 is out of range w.h.p.)
    const long long* p = (const long long*)ei;
    int lane = threadIdx.x;
    long long v = p[lane];
    int ok = (v >= 0 && v < n);
    unsigned m = __ballot_sync(0xffffffffu, ok);
    if (lane == 0) g_is64 = (m == 0xffffffffu) ? 1 : 0;
}

__global__ void k_convert(const void* __restrict__ ei, int E) {
    int i = blockIdx.x * blockDim.x + threadIdx.x;
    if (i >= E) return;
    if (g_is64) {
        const long long* p = (const long long*)ei;
        g_src[i] = (int)p[i];
        g_dst[i] = (int)p[E + i];
    } else {
        const int* p = (const int*)ei;
        g_src[i] = p[i];
        g_dst[i] = p[E + i];
    }
}

__device__ __forceinline__ float lrelu(float x) {
    return x > 0.f ? x : NEG_SLOPE * x;
}

// ---------------- K4: softmax denominators (edges + self loops) -------------
__global__ void k_den(int E, int n) {
    int idx = blockIdx.x * blockDim.x + threadIdx.x;
    int tot = E + n;
    if (idx >= tot) return;
    int s, d;
    if (idx < E) { s = g_src[idx]; d = g_dst[idx]; }
    else         { s = d = idx - E; }
    float4 as = *(const float4*)&g_als[s * 4];
    float4 ad = *(const float4*)&g_ald[d * 4];
    atomicAdd(&g_den[d * 4 + 0], __expf(lrelu(as.x + ad.x)));
    atomicAdd(&g_den[d * 4 + 1], __expf(lrelu(as.y + ad.y)));
    atomicAdd(&g_den[d * 4 + 2], __expf(lrelu(as.z + ad.z)));
    atomicAdd(&g_den[d * 4 + 3], __expf(lrelu(as.w + ad.w)));
}

// ---------------- K5: weighted scatter-aggregate (warp per edge) ------------
__global__ void k_agg(int E, int n) {
    int warp = (blockIdx.x * blockDim.x + threadIdx.x) >> 5;
    int lane = threadIdx.x & 31;
    int tot = E + n;
    if (warp >= tot) return;
    int s, d;
    if (warp < E) { s = g_src[warp]; d = g_dst[warp]; }
    else          { s = d = warp - E; }
    float4 as = *(const float4*)&g_als[s * 4];   // broadcast within warp
    float4 ad = *(const float4*)&g_ald[d * 4];
    float4 dn = *(const float4*)&g_den[d * 4];
    float alpha[4];
    alpha[0] = __expf(lrelu(as.x + ad.x)) / (dn.x + 1e-16f);
    alpha[1] = __expf(lrelu(as.y + ad.y)) / (dn.y + 1e-16f);
    alpha[2] = __expf(lrelu(as.z + ad.z)) / (dn.z + 1e-16f);
    alpha[3] = __expf(lrelu(as.w + ad.w)) / (dn.w + 1e-16f);

    const float* hs = &g_h[(size_t)s * 256];
    float*       oa = &g_acc[(size_t)d * 256];

    int o1 = lane * 4;           // channels 0..127  -> heads 0/1
    int o2 = 128 + lane * 4;     // channels 128..255-> heads 2/3
    float w1 = alpha[lane >> 4];
    float w2 = alpha[2 + (lane >> 4)];
    float4 h1 = *(const float4*)&hs[o1];
    float4 h2 = *(const float4*)&hs[o2];
    atomicAdd(&oa[o1 + 0], h1.x * w1);
    atomicAdd(&oa[o1 + 1], h1.y * w1);
    atomicAdd(&oa[o1 + 2], h1.z * w1);
    atomicAdd(&oa[o1 + 3], h1.w * w1);
    atomicAdd(&oa[o2 + 0], h2.x * w2);
    atomicAdd(&oa[o2 + 1], h2.y * w2);
    atomicAdd(&oa[o2 + 2], h2.z * w2);
    atomicAdd(&oa[o2 + 3], h2.w * w2);
}

// ---------------- K6: LayerNorm (warp per node) -----------------------------
__global__ void k_ln(const float* __restrict__ gamma,
                     const float* __restrict__ beta,
                     float* __restrict__ out, int n) {
    int warp = (blockIdx.x * blockDim.x + threadIdx.x) >> 5;
    int lane = threadIdx.x & 31;
    if (warp >= n) return;
    const float* y = &g_acc[(size_t)warp * 256];
    float4 v1 = *(const float4*)&y[lane * 4];
    float4 v2 = *(const float4*)&y[128 + lane * 4];
    float s  = v1.x + v1.y + v1.z + v1.w + v2.x + v2.y + v2.z + v2.w;
    float sq = v1.x*v1.x + v1.y*v1.y + v1.z*v1.z + v1.w*v1.w
             + v2.x*v2.x + v2.y*v2.y + v2.z*v2.z + v2.w*v2.w;
    #pragma unroll
    for (int off = 16; off >= 1; off >>= 1) {
        s  += __shfl_xor_sync(0xffffffffu, s,  off);
        sq += __shfl_xor_sync(0xffffffffu, sq, off);
    }
    float mu   = s * (1.f / 256.f);
    float var  = sq * (1.f / 256.f) - mu * mu;
    float rstd = rsqrtf(var + LN_EPS);
    float4 g1 = *(const float4*)&gamma[lane * 4];
    float4 g2 = *(const float4*)&gamma[128 + lane * 4];
    float4 b1 = *(const float4*)&beta[lane * 4];
    float4 b2 = *(const float4*)&beta[128 + lane * 4];
    float4 o1, o2;
    o1.x = g1.x * (v1.x - mu) * rstd + b1.x;
    o1.y = g1.y * (v1.y - mu) * rstd + b1.y;
    o1.z = g1.z * (v1.z - mu) * rstd + b1.z;
    o1.w = g1.w * (v1.w - mu) * rstd + b1.w;
    o2.x = g2.x * (v2.x - mu) * rstd + b2.x;
    o2.y = g2.y * (v2.y - mu) * rstd + b2.y;
    o2.z = g2.z * (v2.z - mu) * rstd + b2.z;
    o2.w = g2.w * (v2.w - mu) * rstd + b2.w;
    *(float4*)&out[(size_t)warp * 256 + lane * 4]       = o1;
    *(float4*)&out[(size_t)warp * 256 + 128 + lane * 4] = o2;
}

// ---------------- launch ----------------------------------------------------
extern "C" void kernel_launch(void* const* d_in, const int* in_sizes, int n_in,
                              void* d_out, int out_size) {
    const float* x        = (const float*)d_in[0];
    const void*  ei       = d_in[1];
    const float* W        = (const float*)d_in[2];
    const float* a_src    = (const float*)d_in[3];
    const float* a_dst    = (const float*)d_in[4];
    const float* bias_gat = (const float*)d_in[5];
    const float* W_res    = (const float*)d_in[6];
    const float* b_res    = (const float*)d_in[7];
    const float* gamma    = (const float*)d_in[8];
    const float* beta     = (const float*)d_in[9];
    float* out = (float*)d_out;

    int n = in_sizes[0] / DIMK;          // 50000
    int E = in_sizes[1] / 2;             // 800000
    if (n > NMAX) n = NMAX;
    if (E > EMAX) E = EMAX;
    int tot = E + n;

    k_copyB<<<(DIMK * 128 + 255) / 256, 256>>>(W, W_res);

    dim3 gg(4, (n + 63) / 64);
    k_gemm<<<gg, 256>>>(x, b_res, bias_gat, n);

    k_al<<<(n * 32 + 255) / 256, 256>>>(a_src, a_dst, n);

    k_detect<<<1, 32>>>(ei, n);
    k_convert<<<(E + 255) / 256, 256>>>(ei, E);

    k_den<<<(tot + 255) / 256, 256>>>(E, n);
    k_agg<<<((tot * 32) + 255) / 256, 256>>>(E, n);
    k_ln<<<(n * 32 + 255) / 256, 256>>>(gamma, beta, out, n);
}

// round 2
// speedup vs baseline: 1.8772x; 1.8772x over previous
#include <cuda_runtime.h>

#define NMAX   50000
#define DIMK   256
#define HN     4
#define EMAX   800000
#define TOTMAX (EMAX + NMAX)
#define NEG_SLOPE 0.2f
#define LN_EPS 1e-5f

// ---------------- static device scratch (no allocations allowed) ------------
__device__ float g_B[DIMK * 512];          // concat(W, W_res): 512 KB
__device__ float g_h[NMAX * DIMK];         // h = x@W              : 51 MB
__device__ float g_acc[NMAX * DIMK];       // x@W_res + biases     : 51 MB
__device__ float g_als[NMAX * HN];         // attn logits (src side)
__device__ float g_ald[NMAX * HN];         // attn logits (dst side)
__device__ int   g_src[EMAX];
__device__ int   g_dst[EMAX];
__device__ int   g_cnt[NMAX];              // degree incl. self loop
__device__ int   g_off[NMAX];              // CSR offsets
__device__ int   g_cur[NMAX];              // scatter cursors
__device__ int   g_csr[TOTMAX];            // CSR: src node ids
__device__ int   g_is64;

// ---------------- K: stage B = [W | W_res] ----------------------------------
__global__ void k_copyB(const float* __restrict__ W, const float* __restrict__ Wres) {
    int idx = blockIdx.x * blockDim.x + threadIdx.x;   // 0 .. 256*128-1
    if (idx >= DIMK * 128) return;
    int k  = idx >> 7;
    int j  = (idx & 127) * 4;
    float4 v;
    if (j < 256) v = *(const float4*)&W[k * 256 + j];
    else         v = *(const float4*)&Wres[k * 256 + j - 256];
    *(float4*)&g_B[k * 512 + j] = v;
}

// ---------------- K: init cnt (self loop) / cur -----------------------------
__global__ void k_zero(int n) {
    int i = blockIdx.x * blockDim.x + threadIdx.x;
    if (i < n) { g_cnt[i] = 1; g_cur[i] = 0; }
}

// ---------------- K: edge-index dtype detect --------------------------------
__global__ void k_detect(const void* __restrict__ ei, int n) {
    const long long* p = (const long long*)ei;
    int lane = threadIdx.x;
    long long v = p[lane];
    int ok = (v >= 0 && v < n);
    unsigned m = __ballot_sync(0xffffffffu, ok);
    if (lane == 0) g_is64 = (m == 0xffffffffu) ? 1 : 0;
}

// ---------------- K: convert + histogram ------------------------------------
__global__ void k_hist(const void* __restrict__ ei, int E) {
    int i = blockIdx.x * blockDim.x + threadIdx.x;
    if (i >= E) return;
    int s, d;
    if (g_is64) {
        const long long* p = (const long long*)ei;
        s = (int)p[i];
        d = (int)p[E + i];
    } else {
        const int* p = (const int*)ei;
        s = p[i];
        d = p[E + i];
    }
    g_src[i] = s;
    g_dst[i] = d;
    atomicAdd(&g_cnt[d], 1);
}

// ---------------- K: single-block exclusive scan over cnt -------------------
__global__ __launch_bounds__(1024) void k_scan(int n) {
    __shared__ int sm[1024];
    int t = threadIdx.x;
    int CH = (n + 1023) >> 10;
    int base = t * CH;
    int s = 0;
    for (int i = 0; i < CH; i++) {
        int idx = base + i;
        if (idx < n) s += g_cnt[idx];
    }
    sm[t] = s;
    __syncthreads();
    for (int off = 1; off < 1024; off <<= 1) {
        int v = 0;
        if (t >= off) v = sm[t - off];
        __syncthreads();
        sm[t] += v;
        __syncthreads();
    }
    int run = (t == 0) ? 0 : sm[t - 1];
    for (int i = 0; i < CH; i++) {
        int idx = base + i;
        if (idx < n) { g_off[idx] = run; run += g_cnt[idx]; }
    }
}

// ---------------- K: scatter edges into CSR (incl. self loops) --------------
__global__ void k_fill(int E, int n) {
    int i = blockIdx.x * blockDim.x + threadIdx.x;
    int tot = E + n;
    if (i >= tot) return;
    int s, d;
    if (i < E) { s = g_src[i]; d = g_dst[i]; }
    else       { s = d = i - E; }
    int pos = g_off[d] + atomicAdd(&g_cur[d], 1);
    g_csr[pos] = s;
}

// ---------------- K: fused GEMM  X[n,256] @ B[256,512] (128x128 tile) -------
// cols 0..255 -> g_h ; cols 256..511 -> g_acc = x@W_res + b_res + bias_gat
__global__ __launch_bounds__(256) void k_gemm(const float* __restrict__ X,
                                              const float* __restrict__ b_res,
                                              const float* __restrict__ bias_gat,
                                              int n) {
    __shared__ float As[16][132];   // transposed A tile (k-major), padded
    __shared__ float Bs[16][128];
    int t  = threadIdx.x;
    int tx = t & 15;                // 0..15
    int ty = t >> 4;                // 0..15
    int rowBase = blockIdx.y * 128;
    int colBase = blockIdx.x * 128;

    float acc[8][8];
    #pragma unroll
    for (int i = 0; i < 8; i++)
        #pragma unroll
        for (int j = 0; j < 8; j++) acc[i][j] = 0.f;

    int ar  = t >> 2;               // 0..63
    int ac4 = (t & 3) * 4;          // 0,4,8,12
    int br  = t >> 5;               // 0..7
    int bc4 = (t & 31) * 4;         // 0..124

    for (int k0 = 0; k0 < 256; k0 += 16) {
        #pragma unroll
        for (int q = 0; q < 2; q++) {
            int r  = ar + q * 64;
            int gr = rowBase + r;
            float4 v = make_float4(0.f, 0.f, 0.f, 0.f);
            if (gr < n) v = *(const float4*)&X[gr * 256 + k0 + ac4];
            As[ac4 + 0][r] = v.x;
            As[ac4 + 1][r] = v.y;
            As[ac4 + 2][r] = v.z;
            As[ac4 + 3][r] = v.w;
            int rb = br + q * 8;
            *(float4*)&Bs[rb][bc4] =
                *(const float4*)&g_B[(k0 + rb) * 512 + colBase + bc4];
        }
        __syncthreads();
        #pragma unroll
        for (int kk = 0; kk < 16; kk++) {
            float4 a0 = *(float4*)&As[kk][ty * 4];
            float4 a1 = *(float4*)&As[kk][64 + ty * 4];
            float4 b0 = *(float4*)&Bs[kk][tx * 4];
            float4 b1 = *(float4*)&Bs[kk][64 + tx * 4];
            float av[8] = {a0.x, a0.y, a0.z, a0.w, a1.x, a1.y, a1.z, a1.w};
            float bv[8] = {b0.x, b0.y, b0.z, b0.w, b1.x, b1.y, b1.z, b1.w};
            #pragma unroll
            for (int i = 0; i < 8; i++)
                #pragma unroll
                for (int j = 0; j < 8; j++)
                    acc[i][j] += av[i] * bv[j];
        }
        __syncthreads();
    }
    // epilogue
    #pragma unroll
    for (int jh = 0; jh < 2; jh++) {
        int colg = colBase + jh * 64 + tx * 4;
        if (colg < 256) {
            #pragma unroll
            for (int ih = 0; ih < 2; ih++)
                #pragma unroll
                for (int i = 0; i < 4; i++) {
                    int gr = rowBase + ih * 64 + ty * 4 + i;
                    if (gr >= n) continue;
                    int ii = ih * 4 + i;
                    *(float4*)&g_h[(size_t)gr * 256 + colg] =
                        make_float4(acc[ii][jh*4+0], acc[ii][jh*4+1],
                                    acc[ii][jh*4+2], acc[ii][jh*4+3]);
                }
        } else {
            int c = colg - 256;
            float4 bb = *(const float4*)&b_res[c];
            float4 bg = *(const float4*)&bias_gat[c];
            float bx = bb.x + bg.x, by = bb.y + bg.y, bz = bb.z + bg.z, bw = bb.w + bg.w;
            #pragma unroll
            for (int ih = 0; ih < 2; ih++)
                #pragma unroll
                for (int i = 0; i < 4; i++) {
                    int gr = rowBase + ih * 64 + ty * 4 + i;
                    if (gr >= n) continue;
                    int ii = ih * 4 + i;
                    *(float4*)&g_acc[(size_t)gr * 256 + c] =
                        make_float4(acc[ii][jh*4+0] + bx, acc[ii][jh*4+1] + by,
                                    acc[ii][jh*4+2] + bz, acc[ii][jh*4+3] + bw);
                }
        }
    }
}

// ---------------- K: per-node attention logits ------------------------------
__global__ void k_al(const float* __restrict__ a_src,
                     const float* __restrict__ a_dst, int n) {
    int warp = (blockIdx.x * blockDim.x + threadIdx.x) >> 5;
    int lane = threadIdx.x & 31;
    if (warp >= n) return;
    const float* hrow = &g_h[(size_t)warp * 256];
    float4 h1 = *(const float4*)&hrow[lane * 4];
    float4 h2 = *(const float4*)&hrow[128 + lane * 4];
    float4 a1 = *(const float4*)&a_src[lane * 4];
    float4 a2 = *(const float4*)&a_src[128 + lane * 4];
    float4 c1 = *(const float4*)&a_dst[lane * 4];
    float4 c2 = *(const float4*)&a_dst[128 + lane * 4];
    float s1 = h1.x*a1.x + h1.y*a1.y + h1.z*a1.z + h1.w*a1.w;  // heads 0/1
    float s2 = h2.x*a2.x + h2.y*a2.y + h2.z*a2.z + h2.w*a2.w;  // heads 2/3
    float d1 = h1.x*c1.x + h1.y*c1.y + h1.z*c1.z + h1.w*c1.w;
    float d2 = h2.x*c2.x + h2.y*c2.y + h2.z*c2.z + h2.w*c2.w;
    #pragma unroll
    for (int off = 8; off >= 1; off >>= 1) {
        s1 += __shfl_xor_sync(0xffffffffu, s1, off);
        s2 += __shfl_xor_sync(0xffffffffu, s2, off);
        d1 += __shfl_xor_sync(0xffffffffu, d1, off);
        d2 += __shfl_xor_sync(0xffffffffu, d2, off);
    }
    if (lane == 0) {
        g_als[warp * 4 + 0] = s1;  g_als[warp * 4 + 2] = s2;
        g_ald[warp * 4 + 0] = d1;  g_ald[warp * 4 + 2] = d2;
    } else if (lane == 16) {
        g_als[warp * 4 + 1] = s1;  g_als[warp * 4 + 3] = s2;
        g_ald[warp * 4 + 1] = d1;  g_ald[warp * 4 + 3] = d2;
    }
}

__device__ __forceinline__ float lrelu(float x) {
    return x > 0.f ? x : NEG_SLOPE * x;
}

// ---------------- K: CSR aggregate + residual + LayerNorm (warp/dst) --------
__global__ __launch_bounds__(256) void k_aggln(const float* __restrict__ gamma,
                                               const float* __restrict__ beta,
                                               float* __restrict__ out, int n) {
    int warp = (blockIdx.x * blockDim.x + threadIdx.x) >> 5;
    int lane = threadIdx.x & 31;
    if (warp >= n) return;
    int d = warp;
    int start = g_off[d];
    int end   = start + g_cnt[d];

    float4 ad = *(const float4*)&g_ald[d * 4];

    // pass 1: softmax denominators (edges distributed over lanes)
    float d0 = 0.f, d1 = 0.f, d2 = 0.f, d3 = 0.f;
    for (int e = start + lane; e < end; e += 32) {
        int s = g_csr[e];
        float4 as = *(const float4*)&g_als[s * 4];
        d0 += __expf(lrelu(as.x + ad.x));
        d1 += __expf(lrelu(as.y + ad.y));
        d2 += __expf(lrelu(as.z + ad.z));
        d3 += __expf(lrelu(as.w + ad.w));
    }
    #pragma unroll
    for (int off = 16; off >= 1; off >>= 1) {
        d0 += __shfl_xor_sync(0xffffffffu, d0, off);
        d1 += __shfl_xor_sync(0xffffffffu, d1, off);
        d2 += __shfl_xor_sync(0xffffffffu, d2, off);
        d3 += __shfl_xor_sync(0xffffffffu, d3, off);
    }
    int h = lane >> 3;    // this lane's channels [lane*8, lane*8+8) -> head
    float dh   = (h == 0) ? d0 : (h == 1) ? d1 : (h == 2) ? d2 : d3;
    float rden = 1.f / (dh + 1e-16f);
    float aldh = (h == 0) ? ad.x : (h == 1) ? ad.y : (h == 2) ? ad.z : ad.w;

    // pass 2: weighted gather-accumulate, 8 channels per lane
    int cbase = lane * 8;
    float4 A = make_float4(0.f, 0.f, 0.f, 0.f);
    float4 Bv = make_float4(0.f, 0.f, 0.f, 0.f);
    for (int e = start; e < end; e++) {
        int s = g_csr[e];
        float alpha = __expf(lrelu(g_als[s * 4 + h] + aldh)) * rden;
        const float* hs = &g_h[(size_t)s * 256 + cbase];
        float4 h1 = *(const float4*)hs;
        float4 h2 = *(const float4*)(hs + 4);
        A.x  += alpha * h1.x;  A.y  += alpha * h1.y;
        A.z  += alpha * h1.z;  A.w  += alpha * h1.w;
        Bv.x += alpha * h2.x;  Bv.y += alpha * h2.y;
        Bv.z += alpha * h2.z;  Bv.w += alpha * h2.w;
    }

    // residual: y = agg + (x@W_res + b_res + bias_gat)
    const float* ya = &g_acc[(size_t)d * 256 + cbase];
    float4 r1 = *(const float4*)ya;
    float4 r2 = *(const float4*)(ya + 4);
    float y0 = A.x + r1.x,  y1 = A.y + r1.y,  y2 = A.z + r1.z,  y3 = A.w + r1.w;
    float y4 = Bv.x + r2.x, y5 = Bv.y + r2.y, y6 = Bv.z + r2.z, y7 = Bv.w + r2.w;

    // LayerNorm
    float s  = y0 + y1 + y2 + y3 + y4 + y5 + y6 + y7;
    float sq = y0*y0 + y1*y1 + y2*y2 + y3*y3 + y4*y4 + y5*y5 + y6*y6 + y7*y7;
    #pragma unroll
    for (int off = 16; off >= 1; off >>= 1) {
        s  += __shfl_xor_sync(0xffffffffu, s,  off);
        sq += __shfl_xor_sync(0xffffffffu, sq, off);
    }
    float mu   = s * (1.f / 256.f);
    float var  = sq * (1.f / 256.f) - mu * mu;
    float rstd = rsqrtf(var + LN_EPS);
    float4 g1 = *(const float4*)&gamma[cbase];
    float4 g2 = *(const float4*)&gamma[cbase + 4];
    float4 b1 = *(const float4*)&beta[cbase];
    float4 b2 = *(const float4*)&beta[cbase + 4];
    float4 o1, o2;
    o1.x = g1.x * (y0 - mu) * rstd + b1.x;
    o1.y = g1.y * (y1 - mu) * rstd + b1.y;
    o1.z = g1.z * (y2 - mu) * rstd + b1.z;
    o1.w = g1.w * (y3 - mu) * rstd + b1.w;
    o2.x = g2.x * (y4 - mu) * rstd + b2.x;
    o2.y = g2.y * (y5 - mu) * rstd + b2.y;
    o2.z = g2.z * (y6 - mu) * rstd + b2.z;
    o2.w = g2.w * (y7 - mu) * rstd + b2.w;
    *(float4*)&out[(size_t)d * 256 + cbase]     = o1;
    *(float4*)&out[(size_t)d * 256 + cbase + 4] = o2;
}

// ---------------- launch ----------------------------------------------------
extern "C" void kernel_launch(void* const* d_in, const int* in_sizes, int n_in,
                              void* d_out, int out_size) {
    const float* x        = (const float*)d_in[0];
    const void*  ei       = d_in[1];
    const float* W        = (const float*)d_in[2];
    const float* a_src    = (const float*)d_in[3];
    const float* a_dst    = (const float*)d_in[4];
    const float* bias_gat = (const float*)d_in[5];
    const float* W_res    = (const float*)d_in[6];
    const float* b_res    = (const float*)d_in[7];
    const float* gamma    = (const float*)d_in[8];
    const float* beta     = (const float*)d_in[9];
    float* out = (float*)d_out;

    int n = in_sizes[0] / DIMK;          // 50000
    int E = in_sizes[1] / 2;             // 800000
    if (n > NMAX) n = NMAX;
    if (E > EMAX) E = EMAX;
    int tot = E + n;

    // launch order arranged so ncu (-s 5 -c 1) captures k_gemm
    k_copyB<<<(DIMK * 128 + 255) / 256, 256>>>(W, W_res);          // 0
    k_zero<<<(n + 255) / 256, 256>>>(n);                           // 1
    k_detect<<<1, 32>>>(ei, n);                                    // 2
    k_hist<<<(E + 255) / 256, 256>>>(ei, E);                       // 3
    k_scan<<<1, 1024>>>(n);                                        // 4
    dim3 gg(4, (n + 127) / 128);
    k_gemm<<<gg, 256>>>(x, b_res, bias_gat, n);                    // 5 <- profiled
    k_fill<<<(tot + 255) / 256, 256>>>(E, n);                      // 6
    k_al<<<(n * 32 + 255) / 256, 256>>>(a_src, a_dst, n);          // 7
    k_aggln<<<((n * 32) + 255) / 256, 256>>>(gamma, beta, out, n); // 8
}